// round 5
// baseline (speedup 1.0000x reference)
#include <cuda_runtime.h>
#include <cstdint>
#include <math.h>

#define T_DIM 8192
#define D_DIM 4096
#define E_DIM 64

// ---------------------------------------------------------------------------
// f32x2 packed helpers
// ---------------------------------------------------------------------------
__device__ __forceinline__ unsigned long long pack2(float lo, float hi) {
    unsigned long long r;
    asm("mov.b64 %0, {%1,%2};" : "=l"(r) : "f"(lo), "f"(hi));
    return r;
}
__device__ __forceinline__ float2 unpack2(unsigned long long v) {
    float2 r;
    asm("mov.b64 {%0,%1}, %2;" : "=f"(r.x), "=f"(r.y) : "l"(v));
    return r;
}
__device__ __forceinline__ void fma2(unsigned long long& d,
                                     unsigned long long a,
                                     unsigned long long b) {
    asm("fma.rn.f32x2 %0, %1, %2, %0;" : "+l"(d) : "l"(a), "l"(b));
}

// ---------------------------------------------------------------------------
// JAX threefry2x32, key = threefry_seed(42) = (0, 42); partitionable counters
// ---------------------------------------------------------------------------
__device__ __forceinline__ uint32_t rotl32(uint32_t x, int d) {
    return (x << d) | (x >> (32 - d));
}

__device__ __forceinline__ uint32_t threefry_bits(uint32_t j) {
    uint32_t x0 = 0u, x1 = j;
    const uint32_t k0 = 0u;
    const uint32_t k1 = 42u;
    const uint32_t k2 = 0u ^ 42u ^ 0x1BD11BDAu;
    x0 += k0; x1 += k1;
#define TF_RND(r) { x0 += x1; x1 = rotl32(x1, (r)); x1 ^= x0; }
    TF_RND(13) TF_RND(15) TF_RND(26) TF_RND(6)
    x0 += k1; x1 += k2 + 1u;
    TF_RND(17) TF_RND(29) TF_RND(16) TF_RND(24)
    x0 += k2; x1 += k0 + 2u;
    TF_RND(13) TF_RND(15) TF_RND(26) TF_RND(6)
    x0 += k0; x1 += k1 + 3u;
    TF_RND(17) TF_RND(29) TF_RND(16) TF_RND(24)
    x0 += k1; x1 += k2 + 4u;
    TF_RND(13) TF_RND(15) TF_RND(26) TF_RND(6)
    x0 += k2; x1 += k0 + 5u;
#undef TF_RND
    return x0 ^ x1;   // partitionable: bits = out0 ^ out1
}

// jax.random.uniform bit->float path (same ops/order as the passing kernel)
__device__ __forceinline__ float bits_to_unif(uint32_t bits) {
    float f = __uint_as_float((bits >> 9) | 0x3F800000u) - 1.0f;
    const float minv = 1e-6f;
    const float maxv = 1.0f - 1e-6f;
    float v = __fadd_rn(__fmul_rn(f, maxv - minv), minv);
    return fmaxf(minv, v);
}

// ---------------------------------------------------------------------------
// Fused kernel: GEMM (logits = h @ W^T + bias) + softmax + Gumbel top-k.
// BM=64, BN=64, BK=32, 256 threads, 4x4 micro-tile, f32x2 accumulation.
// A is stored in smem PRE-DUPLICATED as (v,v) 64-bit pairs so the inner loop
// is pure LDS + FFMA2 (no pack movs). Tiles transposed [BK][BM], XOR swizzle.
// ---------------------------------------------------------------------------
struct MainSmem {
    unsigned long long As2[32 * 64];  // 16 KB, A duplicated pairs
    float Bs[32 * 64];                // 8 KB
};
struct EpiSmem {
    float L[64 * 64];                 // 16 KB logits tile
    float S[64 * 64];                 // 16 KB sel scores
};

__global__ __launch_bounds__(256, 1) void router_fused_kernel(
    const float* __restrict__ A,     // h [T, D]
    const float* __restrict__ B,     // W [E=64, D]
    const float* __restrict__ bias,  // [64]
    const int*  __restrict__ kptr,
    float* __restrict__ out_mask,
    float* __restrict__ out_weight,
    float* __restrict__ out_logits)
{
    __shared__ __align__(16) union { MainSmem m; EpiSmem e; } sm;

    const int tid = threadIdx.x;
    const int tx  = tid & 15;   // col group (4 cols)
    const int ty  = tid >> 4;   // row group (4 rows)
    const int bm  = blockIdx.x * 64;

    // Global->smem load slots: 512 float4 per tile per matrix, 2 per thread.
    const int s0 = tid, s1 = tid + 256;
    const int r0 = s0 >> 3, q0 = s0 & 7;   // row in tile, float4-chunk in BK
    const int r1 = s1 >> 3, q1 = s1 & 7;

    const float4* A0 = (const float4*)(A + (size_t)(bm + r0) * D_DIM) + q0;
    const float4* A1 = (const float4*)(A + (size_t)(bm + r1) * D_DIM) + q1;
    const float4* B0 = (const float4*)(B + (size_t)r0 * D_DIM) + q0;
    const float4* B1 = (const float4*)(B + (size_t)r1 * D_DIM) + q1;

    // Swizzled physical column: pm = row ^ (4*kchunk)
    const int pm0 = r0 ^ (q0 << 2);
    const int pm1 = r1 ^ (q1 << 2);

    unsigned long long acc[4][2];
#pragma unroll
    for (int i = 0; i < 4; i++) { acc[i][0] = 0ull; acc[i][1] = 0ull; }

    // Prefetch tile 0
    float4 a0 = A0[0], a1 = A1[0], b0 = B0[0], b1 = B1[0];

    const int NT = D_DIM / 32;
    for (int kt = 0; kt < NT; kt++) {
        // Store current tile; A pre-duplicated as (v,v) pairs.
        sm.m.As2[(q0 * 4 + 0) * 64 + pm0] = pack2(a0.x, a0.x);
        sm.m.As2[(q0 * 4 + 1) * 64 + pm0] = pack2(a0.y, a0.y);
        sm.m.As2[(q0 * 4 + 2) * 64 + pm0] = pack2(a0.z, a0.z);
        sm.m.As2[(q0 * 4 + 3) * 64 + pm0] = pack2(a0.w, a0.w);
        sm.m.As2[(q1 * 4 + 0) * 64 + pm1] = pack2(a1.x, a1.x);
        sm.m.As2[(q1 * 4 + 1) * 64 + pm1] = pack2(a1.y, a1.y);
        sm.m.As2[(q1 * 4 + 2) * 64 + pm1] = pack2(a1.z, a1.z);
        sm.m.As2[(q1 * 4 + 3) * 64 + pm1] = pack2(a1.w, a1.w);
        sm.m.Bs[(q0 * 4 + 0) * 64 + pm0] = b0.x;
        sm.m.Bs[(q0 * 4 + 1) * 64 + pm0] = b0.y;
        sm.m.Bs[(q0 * 4 + 2) * 64 + pm0] = b0.z;
        sm.m.Bs[(q0 * 4 + 3) * 64 + pm0] = b0.w;
        sm.m.Bs[(q1 * 4 + 0) * 64 + pm1] = b1.x;
        sm.m.Bs[(q1 * 4 + 1) * 64 + pm1] = b1.y;
        sm.m.Bs[(q1 * 4 + 2) * 64 + pm1] = b1.z;
        sm.m.Bs[(q1 * 4 + 3) * 64 + pm1] = b1.w;
        __syncthreads();

        // Prefetch next tile (overlaps DRAM latency with compute below)
        if (kt + 1 < NT) {
            const int off = (kt + 1) * 8;
            a0 = A0[off]; a1 = A1[off]; b0 = B0[off]; b1 = B1[off];
        }

#pragma unroll
        for (int k = 0; k < 32; k++) {
            const int sw = (k >> 2) << 2;
            const ulonglong2* ap =
                (const ulonglong2*)&sm.m.As2[k * 64 + ((ty * 4) ^ sw)];
            ulonglong2 a01 = ap[0];
            ulonglong2 a23 = ap[1];
            ulonglong2 bv =
                *(const ulonglong2*)&sm.m.Bs[k * 64 + ((tx * 4) ^ sw)];
            fma2(acc[0][0], a01.x, bv.x); fma2(acc[0][1], a01.x, bv.y);
            fma2(acc[1][0], a01.y, bv.x); fma2(acc[1][1], a01.y, bv.y);
            fma2(acc[2][0], a23.x, bv.x); fma2(acc[2][1], a23.x, bv.y);
            fma2(acc[3][0], a23.y, bv.x); fma2(acc[3][1], a23.y, bv.y);
        }
        __syncthreads();
    }

    // ---- Epilogue part 1: bias add, write logits (gmem + smem stage) ----
    float4 bvec = *(const float4*)(bias + tx * 4);
#pragma unroll
    for (int i = 0; i < 4; i++) {
        float2 p0 = unpack2(acc[i][0]);
        float2 p1 = unpack2(acc[i][1]);
        float4 o;
        o.x = p0.x + bvec.x;
        o.y = p0.y + bvec.y;
        o.z = p1.x + bvec.z;
        o.w = p1.y + bvec.w;
        const int rloc = ty * 4 + i;
        *(float4*)(out_logits + (size_t)(bm + rloc) * 64 + tx * 4) = o;
        *(float4*)(&sm.e.L[rloc * 64 + tx * 4]) = o;
    }
    __syncthreads();

    // ---- Epilogue part 2: softmax + Gumbel top-k, warp-per-row ----
    const int wrp = tid >> 5;          // 0..7 -> rows wrp*8 .. wrp*8+7
    const int ln  = tid & 31;          // lane: experts ln and ln+32
    const int kk  = kptr ? *kptr : 8;

    for (int rr = 0; rr < 8; rr++) {
        const int r    = wrp * 8 + rr;
        const int grow = bm + r;
        const float l0 = sm.e.L[r * 64 + ln];
        const float l1 = sm.e.L[r * 64 + ln + 32];

        const uint32_t j0 = (uint32_t)(grow * 64 + ln);
        const float g0 = -logf(-logf(bits_to_unif(threefry_bits(j0))));
        const float g1 = -logf(-logf(bits_to_unif(threefry_bits(j0 + 32u))));
        const float sc0 = l0 + g0;
        const float sc1 = l1 + g1;
        sm.e.S[r * 64 + ln]      = sc0;
        sm.e.S[r * 64 + ln + 32] = sc1;
        __syncwarp();

        // softmax: one expf per element, shfl reductions
        float m = fmaxf(l0, l1);
#pragma unroll
        for (int d = 16; d >= 1; d >>= 1)
            m = fmaxf(m, __shfl_xor_sync(0xFFFFFFFFu, m, d));
        const float e0 = expf(l0 - m);
        const float e1 = expf(l1 - m);
        float z = e0 + e1;
#pragma unroll
        for (int d = 16; d >= 1; d >>= 1)
            z += __shfl_xor_sync(0xFFFFFFFFu, z, d);
        const float w0 = e0 / z;
        const float w1 = e1 / z;

        // top-k rank count; ties -> lower index (lax.top_k stability)
        int c0 = 0, c1 = 0;
#pragma unroll 16
        for (int i = 0; i < 64; i++) {
            const float v = sm.e.S[r * 64 + i];     // broadcast read
            c0 += (v > sc0) || (v == sc0 && i < ln);
            c1 += (v > sc1) || (v == sc1 && i < ln + 32);
        }

        out_mask[j0]        = (c0 < kk) ? 1.0f : 0.0f;
        out_mask[j0 + 32u]  = (c1 < kk) ? 1.0f : 0.0f;
        out_weight[j0]       = w0;
        out_weight[j0 + 32u] = w1;
        __syncwarp();   // protect S row before next iteration reuses region
    }
}

// ---------------------------------------------------------------------------
// Output layout: tuple (mask, weight, logits) concatenated as f32.
// ---------------------------------------------------------------------------
extern "C" void kernel_launch(void* const* d_in, const int* in_sizes, int n_in,
                              void* d_out, int out_size) {
    const float* h    = (const float*)d_in[0];
    const float* W    = (const float*)d_in[1];
    const float* bias = (const float*)d_in[2];
    const int*   kptr = (n_in > 3) ? (const int*)d_in[3] : nullptr;

    float* out        = (float*)d_out;
    float* out_mask   = out;
    float* out_weight = out + (size_t)T_DIM * E_DIM;
    float* out_logits = out + 2 * (size_t)T_DIM * E_DIM;

    router_fused_kernel<<<T_DIM / 64, 256>>>(h, W, bias, kptr,
                                             out_mask, out_weight, out_logits);
}